// round 9
// baseline (speedup 1.0000x reference)
#include <cuda_runtime.h>
#include <cuda_bf16.h>
#include <math.h>
#include <stdint.h>

#define CB   256
#define CV   50
#define CN   32
#define CD   128
#define CND  4096
#define CG   1560
#define CL   12
#define CCS  10
#define CHH  384
#define CHS  64
#define COUT 128
#define CKLH (CHH * CCS)          // 3840
#define CKO  (CV * CHH)           // 19200
#define SPLITO 12
#define NNE  10001                // embed rows

// ---- scratch ----
__device__ float g_XO[(size_t)CV * CB * CG];          // 80 MB
__device__ float g_xo[CB * CG];
__device__ float g_c[CB * CHH];
__device__ float g_h[CB * CHH];
__device__ float g_tmpdis[CCS * CB];
__device__ float g_h_all[(size_t)CV * CB * CHH];
__device__ float g_theme_all[(size_t)CV * CB * CHH];
__device__ __align__(16) __nv_bfloat16 g_lhhi[(size_t)CV * CB * CKLH];
__device__ __align__(16) __nv_bfloat16 g_lhlo[(size_t)CV * CB * CKLH];
__device__ __align__(16) __nv_bfloat16 g_ehi[(size_t)NNE * CD];
__device__ __align__(16) __nv_bfloat16 g_elo[(size_t)NNE * CD];
__device__ __align__(16) __nv_bfloat16 g_kwhi[(size_t)CG * CND];
__device__ __align__(16) __nv_bfloat16 g_kwlo[(size_t)CG * CND];
__device__ __align__(16) __nv_bfloat16 g_cwhi[(size_t)CHH * CKLH];
__device__ __align__(16) __nv_bfloat16 g_cwlo[(size_t)CHH * CKLH];
__device__ __align__(16) __nv_bfloat16 g_rwhi[(size_t)CG * CHH];
__device__ __align__(16) __nv_bfloat16 g_rwlo[(size_t)CG * CHH];
__device__ __align__(16) __nv_bfloat16 g_hhi[CB * CHH];
__device__ __align__(16) __nv_bfloat16 g_hlo[CB * CHH];
__device__ __align__(16) __nv_bfloat16 g_rnnhi[(size_t)CB * CKO];
__device__ __align__(16) __nv_bfloat16 g_rnnlo[(size_t)CB * CKO];
__device__ __align__(16) __nv_bfloat16 g_owhi[(size_t)COUT * CKO];
__device__ __align__(16) __nv_bfloat16 g_owlo[(size_t)COUT * CKO];
__device__ float g_kwlast[CG];
__device__ float g_rwlast[CG];

__device__ __forceinline__ float sigmoidf(float x) { return 1.0f / (1.0f + expf(-x)); }

// ---- warp-mma helpers ----
__device__ __forceinline__ uint32_t smem_u32(const void* p) {
    uint32_t a;
    asm("{ .reg .u64 t; cvta.to.shared.u64 t, %1; cvt.u32.u64 %0, t; }" : "=r"(a) : "l"(p));
    return a;
}
#define LDSM_X4(r0, r1, r2, r3, addr) \
    asm volatile("ldmatrix.sync.aligned.m8n8.x4.shared.b16 {%0,%1,%2,%3}, [%4];" \
                 : "=r"(r0), "=r"(r1), "=r"(r2), "=r"(r3) : "r"(addr))
#define MMA_BF16(c, a, b0, b1) \
    asm volatile("mma.sync.aligned.m16n8k16.row.col.f32.bf16.bf16.f32 " \
                 "{%0,%1,%2,%3}, {%4,%5,%6,%7}, {%8,%9}, {%0,%1,%2,%3};" \
                 : "+f"((c)[0]), "+f"((c)[1]), "+f"((c)[2]), "+f"((c)[3]) \
                 : "r"((a)[0]), "r"((a)[1]), "r"((a)[2]), "r"((a)[3]), "r"(b0), "r"(b1))
#define CP16(dst, src) \
    asm volatile("cp.async.cg.shared.global [%0], [%1], 16;" :: "r"(dst), "l"(src))
#define CP16Z(dst, src, sz) \
    asm volatile("cp.async.cg.shared.global [%0], [%1], 16, %2;" :: "r"(dst), "l"(src), "r"(sz))
#define CP_COMMIT() asm volatile("cp.async.commit_group;" ::: "memory")
#define CP_WAIT1()  asm volatile("cp.async.wait_group 1;" ::: "memory")
#define CP_WAIT0()  asm volatile("cp.async.wait_group 0;" ::: "memory")

#define OFF_AHI 0
#define OFF_ALO 10240
#define OFF_BHI 20480
#define OFF_BLO 30720
#define STG     40960
#define DSM_TOTAL (2 * STG)

// ---- init ----
__global__ void k_init() {
    int i = blockIdx.x * blockDim.x + threadIdx.x;
    if (i < CB * CHH) {
        g_c[i] = 0.f; g_h[i] = 0.f;
        g_hhi[i] = __float2bfloat16(0.f); g_hlo[i] = __float2bfloat16(0.f);
    }
}
__global__ void k_outinit(const float* __restrict__ ob, float* __restrict__ out) {
    int i = blockIdx.x * blockDim.x + threadIdx.x;
    if (i < CB * COUT) out[i] = ob[i & (COUT - 1)];
}

// ---- fp32 -> bf16 hi/lo splits ----
__global__ void k_cvt_embed(const float* __restrict__ embed) {
    int i = blockIdx.x * blockDim.x + threadIdx.x;
    if (i >= NNE * CD) return;
    float f = embed[i];
    __nv_bfloat16 hi = __float2bfloat16(f);
    g_ehi[i] = hi;
    g_elo[i] = __float2bfloat16(f - __bfloat162float(hi));
}
__global__ void k_cvt_kw(const float* __restrict__ kw) {
    size_t i = (size_t)blockIdx.x * blockDim.x + threadIdx.x;
    if (i >= (size_t)CG * CND) return;
    int g = (int)(i / CND), k = (int)(i % CND);
    float f = kw[(size_t)g * (CND + 1) + k];
    __nv_bfloat16 hi = __float2bfloat16(f);
    g_kwhi[i] = hi;
    g_kwlo[i] = __float2bfloat16(f - __bfloat162float(hi));
}
__global__ void k_cvt_last(const float* __restrict__ kw, const float* __restrict__ rw) {
    int g = blockIdx.x * blockDim.x + threadIdx.x;
    if (g < CG) {
        g_kwlast[g] = kw[(size_t)g * (CND + 1) + CND];
        g_rwlast[g] = rw[(size_t)g * (CHH + 1) + CHH];
    }
}
__global__ void k_cvt_cw(const float* __restrict__ cw) {
    int i = blockIdx.x * blockDim.x + threadIdx.x;
    if (i >= CHH * CKLH) return;
    float f = cw[i];
    __nv_bfloat16 hi = __float2bfloat16(f);
    g_cwhi[i] = hi;
    g_cwlo[i] = __float2bfloat16(f - __bfloat162float(hi));
}
__global__ void k_cvt_rw(const float* __restrict__ rw) {
    int i = blockIdx.x * blockDim.x + threadIdx.x;
    if (i >= CG * CHH) return;
    int g = i / CHH, k = i - g * CHH;
    float f = rw[(size_t)g * (CHH + 1) + k];
    __nv_bfloat16 hi = __float2bfloat16(f);
    g_rwhi[i] = hi;
    g_rwlo[i] = __float2bfloat16(f - __bfloat162float(hi));
}
__global__ void k_cvt_ow(const float* __restrict__ ow) {
    size_t i = (size_t)blockIdx.x * blockDim.x + threadIdx.x;
    if (i >= (size_t)COUT * CKO) return;
    float f = ow[i];
    __nv_bfloat16 hi = __float2bfloat16(f);
    g_owhi[i] = hi;
    g_owlo[i] = __float2bfloat16(f - __bfloat162float(hi));
}

// ---- shared compute core: one BK=32 chunk of 128x128 via HMMA hi/lo ----
__device__ __forceinline__ void mma_chunk(char* base, int lane, int wm, int wn,
                                          float acc[4][4][4]) {
    const int lrow = lane & 15;
    const int lcolB = (lane >> 4) * 16;
    #pragma unroll
    for (int ks = 0; ks < 2; ks++) {
        const int colb = ks * 32 + lcolB;
        uint32_t ahi[4][4], alo[4][4], bhi[2][4], blo[2][4];
        #pragma unroll
        for (int mf = 0; mf < 4; mf++) {
            int rbase = (wm * 64 + mf * 16 + lrow) * 80 + colb;
            LDSM_X4(ahi[mf][0], ahi[mf][1], ahi[mf][2], ahi[mf][3], smem_u32(base + OFF_AHI + rbase));
            LDSM_X4(alo[mf][0], alo[mf][1], alo[mf][2], alo[mf][3], smem_u32(base + OFF_ALO + rbase));
        }
        #pragma unroll
        for (int np = 0; np < 2; np++) {
            int rbase = (wn * 32 + np * 16 + lrow) * 80 + colb;
            LDSM_X4(bhi[np][0], bhi[np][1], bhi[np][2], bhi[np][3], smem_u32(base + OFF_BHI + rbase));
            LDSM_X4(blo[np][0], blo[np][1], blo[np][2], blo[np][3], smem_u32(base + OFF_BLO + rbase));
        }
        #pragma unroll
        for (int mf = 0; mf < 4; mf++) {
            #pragma unroll
            for (int nf = 0; nf < 4; nf++) {
                int np = nf >> 1, h8 = nf & 1;
                MMA_BF16(acc[mf][nf], ahi[mf], bhi[np][h8], bhi[np][h8 + 2]);
                MMA_BF16(acc[mf][nf], ahi[mf], blo[np][h8], blo[np][h8 + 2]);
                MMA_BF16(acc[mf][nf], alo[mf], bhi[np][h8], bhi[np][h8 + 2]);
            }
        }
    }
}

// ---- big GEMM: XO[v][b][g], cp.async 2-stage pipeline (unchanged from R8) ----
__global__ __launch_bounds__(256) void k_gemm_mma(const float* __restrict__ kb,
                                                  const float* __restrict__ time_,
                                                  const int* __restrict__ node_ids) {
    extern __shared__ char dsm[];
    const int tid = threadIdx.x;
    const int lane = tid & 31, wid = tid >> 5;
    const int wm = wid >> 2, wn = wid & 3;
    const int m0 = blockIdx.x * 128, n0 = blockIdx.y * 128;
    const int NC = CND / 32;

    float acc[4][4][4];
    #pragma unroll
    for (int i = 0; i < 4; i++)
        #pragma unroll
        for (int j = 0; j < 4; j++)
            #pragma unroll
            for (int z = 0; z < 4; z++) acc[i][j][z] = 0.f;

    auto load_stage = [&](int kc, int stage) {
        #pragma unroll
        for (int it = 0; it < 2; it++) {
            int s = tid + it * 256;
            int row = s >> 2, q = s & 3;
            int nb = kc >> 2;
            int off = (kc & 3) * 32 + q * 8;
            int id = node_ids[(m0 + row) * CN + nb];
            uint32_t d = smem_u32(dsm + stage * STG + row * 80 + q * 16);
            CP16(d + OFF_AHI, (const char*)(g_ehi + (size_t)id * CD + off));
            CP16(d + OFF_ALO, (const char*)(g_elo + (size_t)id * CD + off));
            int g = n0 + row;
            int gc = g < CG ? g : (CG - 1);
            uint32_t sz = g < CG ? 16u : 0u;
            CP16Z(d + OFF_BHI, (const char*)(g_kwhi + (size_t)gc * CND + kc * 32 + q * 8), sz);
            CP16Z(d + OFF_BLO, (const char*)(g_kwlo + (size_t)gc * CND + kc * 32 + q * 8), sz);
        }
    };

    load_stage(0, 0); CP_COMMIT();
    load_stage(1, 1); CP_COMMIT();
    for (int kc = 0; kc < NC; kc++) {
        if (kc == NC - 1) { CP_WAIT0(); } else { CP_WAIT1(); }
        __syncthreads();
        mma_chunk(dsm + (kc & 1) * STG, lane, wm, wn, acc);
        __syncthreads();
        if (kc + 2 < NC) { load_stage(kc + 2, (kc + 2) & 1); CP_COMMIT(); }
    }

    #pragma unroll
    for (int mf = 0; mf < 4; mf++) {
        #pragma unroll
        for (int hf = 0; hf < 2; hf++) {
            int r = m0 + wm * 64 + mf * 16 + (lane >> 2) + hf * 8;
            int b = r / CV, v = r - b * CV;
            float t = time_[r];
            float* dst = g_XO + ((size_t)v * CB + b) * CG;
            #pragma unroll
            for (int nf = 0; nf < 4; nf++) {
                int g = n0 + wn * 32 + nf * 8 + (lane & 3) * 2;
                float c0 = acc[mf][nf][hf * 2 + 0];
                float c1 = acc[mf][nf][hf * 2 + 1];
                if (g < CG)     dst[g]     = c0 + t * g_kwlast[g] + kb[g];
                if (g + 1 < CG) dst[g + 1] = c1 + t * g_kwlast[g + 1] + kb[g + 1];
            }
        }
    }
}

// ---- per-step rec GEMM via HMMA: xo = h.rw^T + XO + t*rwlast + rb ----
// grid (2, 13), 256 threads, 128x128 tile, K=384 -> 12 chunks
__global__ __launch_bounds__(256) void k_rec_mma(const float* __restrict__ rb,
                                                 const float* __restrict__ time_, int v) {
    extern __shared__ char dsm[];
    const int tid = threadIdx.x;
    const int lane = tid & 31, wid = tid >> 5;
    const int wm = wid >> 2, wn = wid & 3;
    const int m0 = blockIdx.x * 128, n0 = blockIdx.y * 128;
    const int NC = CHH / 32;   // 12

    float acc[4][4][4];
    #pragma unroll
    for (int i = 0; i < 4; i++)
        #pragma unroll
        for (int j = 0; j < 4; j++)
            #pragma unroll
            for (int z = 0; z < 4; z++) acc[i][j][z] = 0.f;

    auto load_stage = [&](int kc, int stage) {
        #pragma unroll
        for (int it = 0; it < 2; it++) {
            int s = tid + it * 256;
            int row = s >> 2, q = s & 3;
            int off = kc * 32 + q * 8;
            uint32_t d = smem_u32(dsm + stage * STG + row * 80 + q * 16);
            CP16(d + OFF_AHI, (const char*)(g_hhi + (m0 + row) * CHH + off));
            CP16(d + OFF_ALO, (const char*)(g_hlo + (m0 + row) * CHH + off));
            int g = n0 + row;
            int gc = g < CG ? g : (CG - 1);
            uint32_t sz = g < CG ? 16u : 0u;
            CP16Z(d + OFF_BHI, (const char*)(g_rwhi + (size_t)gc * CHH + off), sz);
            CP16Z(d + OFF_BLO, (const char*)(g_rwlo + (size_t)gc * CHH + off), sz);
        }
    };

    load_stage(0, 0); CP_COMMIT();
    load_stage(1, 1); CP_COMMIT();
    for (int kc = 0; kc < NC; kc++) {
        if (kc == NC - 1) { CP_WAIT0(); } else { CP_WAIT1(); }
        __syncthreads();
        mma_chunk(dsm + (kc & 1) * STG, lane, wm, wn, acc);
        __syncthreads();
        if (kc + 2 < NC) { load_stage(kc + 2, (kc + 2) & 1); CP_COMMIT(); }
    }

    #pragma unroll
    for (int mf = 0; mf < 4; mf++) {
        #pragma unroll
        for (int hf = 0; hf < 2; hf++) {
            int bb = m0 + wm * 64 + mf * 16 + (lane >> 2) + hf * 8;
            float t = time_[bb * CV + v];
            const float* xop = g_XO + ((size_t)v * CB + bb) * CG;
            float* dst = g_xo + bb * CG;
            #pragma unroll
            for (int nf = 0; nf < 4; nf++) {
                int g = n0 + wn * 32 + nf * 8 + (lane & 3) * 2;
                float c0 = acc[mf][nf][hf * 2 + 0];
                float c1 = acc[mf][nf][hf * 2 + 1];
                if (g < CG)     dst[g]     = c0 + t * g_rwlast[g] + rb[g] + xop[g];
                if (g + 1 < CG) dst[g + 1] = c1 + t * g_rwlast[g + 1] + rb[g + 1] + xop[g + 1];
            }
        }
    }
}

// ---- conv GEMM: writes rnn as bf16 hi/lo ----
__global__ __launch_bounds__(256) void k_conv_mma(const float* __restrict__ cb) {
    extern __shared__ char dsm[];
    const int tid = threadIdx.x;
    const int lane = tid & 31, wid = tid >> 5;
    const int wm = wid >> 2, wn = wid & 3;
    const int m0 = blockIdx.x * 128, n0 = blockIdx.y * 128;
    const int NC = CKLH / 32;

    float acc[4][4][4];
    #pragma unroll
    for (int i = 0; i < 4; i++)
        #pragma unroll
        for (int j = 0; j < 4; j++)
            #pragma unroll
            for (int z = 0; z < 4; z++) acc[i][j][z] = 0.f;

    auto load_stage = [&](int kc, int stage) {
        #pragma unroll
        for (int it = 0; it < 2; it++) {
            int s = tid + it * 256;
            int row = s >> 2, q = s & 3;
            uint32_t d = smem_u32(dsm + stage * STG + row * 80 + q * 16);
            size_t aoff = (size_t)(m0 + row) * CKLH + kc * 32 + q * 8;
            CP16(d + OFF_AHI, (const char*)(g_lhhi + aoff));
            CP16(d + OFF_ALO, (const char*)(g_lhlo + aoff));
            size_t boff = (size_t)(n0 + row) * CKLH + kc * 32 + q * 8;
            CP16(d + OFF_BHI, (const char*)(g_cwhi + boff));
            CP16(d + OFF_BLO, (const char*)(g_cwlo + boff));
        }
    };

    load_stage(0, 0); CP_COMMIT();
    load_stage(1, 1); CP_COMMIT();
    for (int kc = 0; kc < NC; kc++) {
        if (kc == NC - 1) { CP_WAIT0(); } else { CP_WAIT1(); }
        __syncthreads();
        mma_chunk(dsm + (kc & 1) * STG, lane, wm, wn, acc);
        __syncthreads();
        if (kc + 2 < NC) { load_stage(kc + 2, (kc + 2) & 1); CP_COMMIT(); }
    }

    #pragma unroll
    for (int mf = 0; mf < 4; mf++) {
        #pragma unroll
        for (int hf = 0; hf < 2; hf++) {
            int r = m0 + wm * 64 + mf * 16 + (lane >> 2) + hf * 8;
            int v = r >> 8, b = r & (CB - 1);
            const float* th = g_theme_all + (size_t)r * CHH;
            const float* hn = g_h_all + (size_t)r * CHH;
            size_t dbase = (size_t)b * CKO + v * CHH;
            #pragma unroll
            for (int nf = 0; nf < 4; nf++) {
                int o = n0 + wn * 32 + nf * 8 + (lane & 3) * 2;
                float r0 = th[o] * (acc[mf][nf][hf * 2 + 0] + cb[o]) + hn[o];
                float r1 = th[o + 1] * (acc[mf][nf][hf * 2 + 1] + cb[o + 1]) + hn[o + 1];
                __nv_bfloat16 h0 = __float2bfloat16(r0);
                __nv_bfloat16 h1 = __float2bfloat16(r1);
                g_rnnhi[dbase + o]     = h0;
                g_rnnhi[dbase + o + 1] = h1;
                g_rnnlo[dbase + o]     = __float2bfloat16(r0 - __bfloat162float(h0));
                g_rnnlo[dbase + o + 1] = __float2bfloat16(r1 - __bfloat162float(h1));
            }
        }
    }
}

// ---- output GEMM via HMMA split-K: out[b][o] += rnn.ow^T ----
// grid (2, 1, SPLITO), K slice = 1600 = 50 chunks
__global__ __launch_bounds__(256) void k_out_mma(float* __restrict__ out) {
    extern __shared__ char dsm[];
    const int tid = threadIdx.x;
    const int lane = tid & 31, wid = tid >> 5;
    const int wm = wid >> 2, wn = wid & 3;
    const int m0 = blockIdx.x * 128;
    const int kb0 = blockIdx.z * (CKO / SPLITO);
    const int NC = (CKO / SPLITO) / 32;  // 50

    float acc[4][4][4];
    #pragma unroll
    for (int i = 0; i < 4; i++)
        #pragma unroll
        for (int j = 0; j < 4; j++)
            #pragma unroll
            for (int z = 0; z < 4; z++) acc[i][j][z] = 0.f;

    auto load_stage = [&](int kc, int stage) {
        #pragma unroll
        for (int it = 0; it < 2; it++) {
            int s = tid + it * 256;
            int row = s >> 2, q = s & 3;
            int off = kb0 + kc * 32 + q * 8;
            uint32_t d = smem_u32(dsm + stage * STG + row * 80 + q * 16);
            CP16(d + OFF_AHI, (const char*)(g_rnnhi + (size_t)(m0 + row) * CKO + off));
            CP16(d + OFF_ALO, (const char*)(g_rnnlo + (size_t)(m0 + row) * CKO + off));
            CP16(d + OFF_BHI, (const char*)(g_owhi + (size_t)row * CKO + off));
            CP16(d + OFF_BLO, (const char*)(g_owlo + (size_t)row * CKO + off));
        }
    };

    load_stage(0, 0); CP_COMMIT();
    load_stage(1, 1); CP_COMMIT();
    for (int kc = 0; kc < NC; kc++) {
        if (kc == NC - 1) { CP_WAIT0(); } else { CP_WAIT1(); }
        __syncthreads();
        mma_chunk(dsm + (kc & 1) * STG, lane, wm, wn, acc);
        __syncthreads();
        if (kc + 2 < NC) { load_stage(kc + 2, (kc + 2) & 1); CP_COMMIT(); }
    }

    #pragma unroll
    for (int mf = 0; mf < 4; mf++) {
        #pragma unroll
        for (int hf = 0; hf < 2; hf++) {
            int bb = m0 + wm * 64 + mf * 16 + (lane >> 2) + hf * 8;
            #pragma unroll
            for (int nf = 0; nf < 4; nf++) {
                int o = wn * 32 + nf * 8 + (lane & 3) * 2;
                atomicAdd(&out[bb * COUT + o],     acc[mf][nf][hf * 2 + 0]);
                atomicAdd(&out[bb * COUT + o + 1], acc[mf][nf][hf * 2 + 1]);
            }
        }
    }
}

// ---- gate: emits h and lh as bf16 hi/lo ----
__global__ __launch_bounds__(CHH) void k_gate(const float* __restrict__ sw,
                                              const float* __restrict__ sb,
                                              const float* __restrict__ rsw,
                                              const float* __restrict__ rsb,
                                              int v, float* __restrict__ out) {
    const int b = blockIdx.x;
    const int t = threadIdx.x;
    const int slot = v % CCS;
    __shared__ float s24[24];
    __shared__ float sfm[CL], sim[CL];
    __shared__ float sld[CCS];
    __shared__ float smh[CHH];
    __shared__ float ss1[CHS];
    __shared__ float red[6][CHS];

    const float* xo = g_xo + b * CG;
    if (t < 24) s24[t] = xo[t];
    __syncthreads();

    if (t == 0) {
        float m1 = s24[0];
        #pragma unroll
        for (int l = 1; l < CL; l++) m1 = fmaxf(m1, s24[l]);
        float e1[CL], sum1 = 0.f;
        #pragma unroll
        for (int l = 0; l < CL; l++) { e1[l] = expf(s24[l] - m1); sum1 += e1[l]; }
        float inv1 = 1.f / sum1, cum = 0.f, fmsum = 0.f;
        #pragma unroll
        for (int l = 0; l < CL; l++) { cum += e1[l] * inv1; sfm[l] = cum; fmsum += cum; }
        float m2 = s24[12];
        #pragma unroll
        for (int l = 1; l < CL; l++) m2 = fmaxf(m2, s24[12 + l]);
        float e2[CL], sum2 = 0.f;
        #pragma unroll
        for (int l = 0; l < CL; l++) { e2[l] = expf(s24[12 + l] - m2); sum2 += e2[l]; }
        float inv2 = 1.f / sum2, cum2 = 0.f;
        for (int l = CL - 1; l >= 0; l--) { cum2 += e2[l] * inv2; sim[l] = cum2; }
        float dist = 1.f - fmsum / (float)CL;
        g_tmpdis[slot * CB + b] = dist;
        out[CB * COUT + v * CB + b] = dist;
    }
    __syncthreads();

    {
        int l = t >> 5;
        float f  = sigmoidf(xo[24 + t]);
        float i_ = sigmoidf(xo[24 + CHH + t]);
        float o  = sigmoidf(xo[24 + 2 * CHH + t]);
        float ci = tanhf(xo[24 + 3 * CHH + t]);
        float cl = g_c[b * CHH + t];
        float fmv = sfm[l], imv = sim[l], ov = fmv * imv;
        float cnew = ov * (f * cl + i_ * ci) + (fmv - ov) * cl + (imv - ov) * ci;
        float hnew = o * tanhf(cnew);
        g_c[b * CHH + t] = cnew;
        g_h[b * CHH + t] = hnew;
        g_h_all[((size_t)v * CB + b) * CHH + t] = hnew;
        __nv_bfloat16 hh = __float2bfloat16(hnew);
        g_hhi[b * CHH + t] = hh;
        g_hlo[b * CHH + t] = __float2bfloat16(hnew - __bfloat162float(hh));
    }
    __syncthreads();

    if (t == 0) {
        float cumv[CCS];
        float cum = 0.f;
        #pragma unroll
        for (int k = 0; k < CCS; k++) {
            int s = v - (CCS - 1) + k;
            float d = (s >= 0) ? g_tmpdis[(s % CCS) * CB + b] : 0.f;
            cum += d;
            cumv[k] = cum;
        }
        float mx = cumv[0];
        #pragma unroll
        for (int k = 1; k < CCS; k++) mx = fmaxf(mx, cumv[k]);
        float e[CCS], sum = 0.f;
        #pragma unroll
        for (int k = 0; k < CCS; k++) { e[k] = expf(cumv[k] - mx); sum += e[k]; }
        float inv = 1.f / sum;
        #pragma unroll
        for (int k = 0; k < CCS; k++) sld[k] = e[k] * inv;
    }
    __syncthreads();

    {
        float mh = 0.f;
        __nv_bfloat16 lhi[CCS], llo[CCS];
        #pragma unroll
        for (int k = 0; k < CCS; k++) {
            int s = v - (CCS - 1) + k;
            float hv = (s >= 0) ? g_h_all[((size_t)s * CB + b) * CHH + t] : 0.f;
            float lv = hv * sld[k];
            __nv_bfloat16 hi = __float2bfloat16(lv);
            lhi[k] = hi;
            llo[k] = __float2bfloat16(lv - __bfloat162float(hi));
            mh += lv;
        }
        size_t base = ((size_t)v * CB + b) * CKLH + t * CCS;
        #pragma unroll
        for (int k = 0; k < CCS; k++) { g_lhhi[base + k] = lhi[k]; g_lhlo[base + k] = llo[k]; }
        smh[t] = mh * (1.f / (float)CCS);
    }
    __syncthreads();

    {
        int j = t & 63, seg = t >> 6;
        float p = 0.f;
        #pragma unroll
        for (int h = 0; h < 64; h++) p += smh[seg * 64 + h] * sw[j * CHH + seg * 64 + h];
        red[seg][j] = p;
    }
    __syncthreads();
    if (t < CHS) {
        float a = sb[t];
        #pragma unroll
        for (int z = 0; z < 6; z++) a += red[z][t];
        ss1[t] = fmaxf(a, 0.f);
    }
    __syncthreads();

    {
        float a = rsb[t];
        #pragma unroll
        for (int j = 0; j < CHS; j++) a += ss1[j] * rsw[t * CHS + j];
        g_theme_all[((size_t)v * CB + b) * CHH + t] = sigmoidf(a);
    }
}

extern "C" void kernel_launch(void* const* d_in, const int* in_sizes, int n_in,
                              void* d_out, int out_size) {
    const int*   node_ids = (const int*)d_in[0];
    const float* time_    = (const float*)d_in[3];
    const float* embed    = (const float*)d_in[6];
    const float* kw  = (const float*)d_in[7];
    const float* kb  = (const float*)d_in[8];
    const float* rw  = (const float*)d_in[9];
    const float* rb  = (const float*)d_in[10];
    const float* sw  = (const float*)d_in[11];
    const float* sb  = (const float*)d_in[12];
    const float* rsw = (const float*)d_in[13];
    const float* rsb = (const float*)d_in[14];
    const float* cw  = (const float*)d_in[15];
    const float* cb  = (const float*)d_in[16];
    const float* ow  = (const float*)d_in[17];
    const float* ob  = (const float*)d_in[18];
    float* out = (float*)d_out;

    cudaFuncSetAttribute(k_gemm_mma, cudaFuncAttributeMaxDynamicSharedMemorySize, DSM_TOTAL);
    cudaFuncSetAttribute(k_conv_mma, cudaFuncAttributeMaxDynamicSharedMemorySize, DSM_TOTAL);
    cudaFuncSetAttribute(k_rec_mma,  cudaFuncAttributeMaxDynamicSharedMemorySize, DSM_TOTAL);
    cudaFuncSetAttribute(k_out_mma,  cudaFuncAttributeMaxDynamicSharedMemorySize, DSM_TOTAL);

    k_init<<<(CB * CHH + 255) / 256, 256>>>();
    k_outinit<<<(CB * COUT + 255) / 256, 256>>>(ob, out);
    k_cvt_embed<<<(NNE * CD + 255) / 256, 256>>>(embed);
    k_cvt_kw<<<(int)(((size_t)CG * CND + 255) / 256), 256>>>(kw);
    k_cvt_last<<<(CG + 255) / 256, 256>>>(kw, rw);
    k_cvt_cw<<<(CHH * CKLH + 255) / 256, 256>>>(cw);
    k_cvt_rw<<<(CG * CHH + 255) / 256, 256>>>(rw);
    k_cvt_ow<<<(int)(((size_t)COUT * CKO + 255) / 256), 256>>>(ow);
    k_gemm_mma<<<dim3(CB * CV / 128, 13), 256, DSM_TOTAL>>>(kb, time_, node_ids);
    for (int v = 0; v < CV; v++) {
        k_rec_mma<<<dim3(2, 13), 256, DSM_TOTAL>>>(rb, time_, v);
        k_gate<<<CB, CHH>>>(sw, sb, rsw, rsb, v, out);
    }
    k_conv_mma<<<dim3(CB * CV / 128, CHH / 128), 256, DSM_TOTAL>>>(cb);
    k_out_mma<<<dim3(2, 1, SPLITO), 256, DSM_TOTAL>>>(out);
}

// round 10
// speedup vs baseline: 1.1172x; 1.1172x over previous
#include <cuda_runtime.h>
#include <cuda_bf16.h>
#include <math.h>
#include <stdint.h>

#define CB   256
#define CV   50
#define CN   32
#define CD   128
#define CND  4096
#define CG   1560
#define CL   12
#define CCS  10
#define CHH  384
#define CHS  64
#define COUT 128
#define CKLH (CHH * CCS)          // 3840
#define SPLITO 24
#define NNE  10001                // embed rows

// ---- scratch ----
__device__ float g_XO[(size_t)CV * CB * CG];          // 80 MB
__device__ float g_xo[CB * CG];
__device__ float g_c[CB * CHH];
__device__ float g_h[CB * CHH];
__device__ float g_tmpdis[CCS * CB];
__device__ float g_h_all[(size_t)CV * CB * CHH];
__device__ float g_theme_all[(size_t)CV * CB * CHH];
__device__ float g_rnn[(size_t)CB * CV * CHH];
__device__ float g_rwf[(size_t)CG * CHH];             // packed rw (contiguous K)
__device__ __align__(16) __nv_bfloat16 g_lhhi[(size_t)CV * CB * CKLH];
__device__ __align__(16) __nv_bfloat16 g_lhlo[(size_t)CV * CB * CKLH];
__device__ __align__(16) __nv_bfloat16 g_ehi[(size_t)NNE * CD];
__device__ __align__(16) __nv_bfloat16 g_elo[(size_t)NNE * CD];
__device__ __align__(16) __nv_bfloat16 g_kwhi[(size_t)CG * CND];
__device__ __align__(16) __nv_bfloat16 g_kwlo[(size_t)CG * CND];
__device__ __align__(16) __nv_bfloat16 g_cwhi[(size_t)CHH * CKLH];
__device__ __align__(16) __nv_bfloat16 g_cwlo[(size_t)CHH * CKLH];
__device__ float g_kwlast[CG];

__device__ __forceinline__ float sigmoidf(float x) { return 1.0f / (1.0f + expf(-x)); }

// ---- packed f32x2 ----
#define FMA2(acc, a2, b2) \
    asm("fma.rn.f32x2 %0, %1, %2, %3;" : "=l"(acc) : "l"(a2), "l"(b2), "l"(acc))
__device__ __forceinline__ unsigned long long pack2(float x) {
    unsigned u = __float_as_uint(x);
    unsigned long long r;
    asm("mov.b64 %0, {%1, %1};" : "=l"(r) : "r"(u));
    return r;
}
__device__ __forceinline__ float2 unpack2(unsigned long long v) {
    unsigned lo, hi;
    asm("mov.b64 {%0, %1}, %2;" : "=r"(lo), "=r"(hi) : "l"(v));
    return make_float2(__uint_as_float(lo), __uint_as_float(hi));
}

// ---- warp-mma helpers ----
__device__ __forceinline__ uint32_t smem_u32(const void* p) {
    uint32_t a;
    asm("{ .reg .u64 t; cvta.to.shared.u64 t, %1; cvt.u32.u64 %0, t; }" : "=r"(a) : "l"(p));
    return a;
}
#define LDSM_X4(r0, r1, r2, r3, addr) \
    asm volatile("ldmatrix.sync.aligned.m8n8.x4.shared.b16 {%0,%1,%2,%3}, [%4];" \
                 : "=r"(r0), "=r"(r1), "=r"(r2), "=r"(r3) : "r"(addr))
#define MMA_BF16(c, a, b0, b1) \
    asm volatile("mma.sync.aligned.m16n8k16.row.col.f32.bf16.bf16.f32 " \
                 "{%0,%1,%2,%3}, {%4,%5,%6,%7}, {%8,%9}, {%0,%1,%2,%3};" \
                 : "+f"((c)[0]), "+f"((c)[1]), "+f"((c)[2]), "+f"((c)[3]) \
                 : "r"((a)[0]), "r"((a)[1]), "r"((a)[2]), "r"((a)[3]), "r"(b0), "r"(b1))
#define CP16(dst, src) \
    asm volatile("cp.async.cg.shared.global [%0], [%1], 16;" :: "r"(dst), "l"(src))
#define CP16Z(dst, src, sz) \
    asm volatile("cp.async.cg.shared.global [%0], [%1], 16, %2;" :: "r"(dst), "l"(src), "r"(sz))
#define CP_COMMIT() asm volatile("cp.async.commit_group;" ::: "memory")
#define CP_WAIT1()  asm volatile("cp.async.wait_group 1;" ::: "memory")
#define CP_WAIT0()  asm volatile("cp.async.wait_group 0;" ::: "memory")

#define OFF_AHI 0
#define OFF_ALO 10240
#define OFF_BHI 20480
#define OFF_BLO 30720
#define STG     40960
#define DSM_TOTAL (2 * STG)

// ---- init ----
__global__ void k_init() {
    int i = blockIdx.x * blockDim.x + threadIdx.x;
    if (i < CB * CHH) { g_c[i] = 0.f; g_h[i] = 0.f; }
}
__global__ void k_outinit(const float* __restrict__ ob, float* __restrict__ out) {
    int i = blockIdx.x * blockDim.x + threadIdx.x;
    if (i < CB * COUT) out[i] = ob[i & (COUT - 1)];
}

// ---- fp32 -> bf16 hi/lo splits + rw pack ----
__global__ void k_cvt_embed(const float* __restrict__ embed) {
    int i = blockIdx.x * blockDim.x + threadIdx.x;
    if (i >= NNE * CD) return;
    float f = embed[i];
    __nv_bfloat16 hi = __float2bfloat16(f);
    g_ehi[i] = hi;
    g_elo[i] = __float2bfloat16(f - __bfloat162float(hi));
}
__global__ void k_cvt_kw(const float* __restrict__ kw) {
    size_t i = (size_t)blockIdx.x * blockDim.x + threadIdx.x;
    if (i >= (size_t)CG * CND) return;
    int g = (int)(i / CND), k = (int)(i % CND);
    float f = kw[(size_t)g * (CND + 1) + k];
    __nv_bfloat16 hi = __float2bfloat16(f);
    g_kwhi[i] = hi;
    g_kwlo[i] = __float2bfloat16(f - __bfloat162float(hi));
}
__global__ void k_cvt_last(const float* __restrict__ kw) {
    int g = blockIdx.x * blockDim.x + threadIdx.x;
    if (g < CG) g_kwlast[g] = kw[(size_t)g * (CND + 1) + CND];
}
__global__ void k_cvt_cw(const float* __restrict__ cw) {
    int i = blockIdx.x * blockDim.x + threadIdx.x;
    if (i >= CHH * CKLH) return;
    float f = cw[i];
    __nv_bfloat16 hi = __float2bfloat16(f);
    g_cwhi[i] = hi;
    g_cwlo[i] = __float2bfloat16(f - __bfloat162float(hi));
}
__global__ void k_pack_rw(const float* __restrict__ rw) {
    int i = blockIdx.x * blockDim.x + threadIdx.x;
    if (i >= CG * CHH) return;
    int g = i / CHH, k = i - g * CHH;
    g_rwf[i] = rw[(size_t)g * (CHH + 1) + k];
}

// ---- shared HMMA compute core (unchanged from R8) ----
__device__ __forceinline__ void mma_chunk(char* base, int lane, int wm, int wn,
                                          float acc[4][4][4]) {
    const int lrow = lane & 15;
    const int lcolB = (lane >> 4) * 16;
    #pragma unroll
    for (int ks = 0; ks < 2; ks++) {
        const int colb = ks * 32 + lcolB;
        uint32_t ahi[4][4], alo[4][4], bhi[2][4], blo[2][4];
        #pragma unroll
        for (int mf = 0; mf < 4; mf++) {
            int rbase = (wm * 64 + mf * 16 + lrow) * 80 + colb;
            LDSM_X4(ahi[mf][0], ahi[mf][1], ahi[mf][2], ahi[mf][3], smem_u32(base + OFF_AHI + rbase));
            LDSM_X4(alo[mf][0], alo[mf][1], alo[mf][2], alo[mf][3], smem_u32(base + OFF_ALO + rbase));
        }
        #pragma unroll
        for (int np = 0; np < 2; np++) {
            int rbase = (wn * 32 + np * 16 + lrow) * 80 + colb;
            LDSM_X4(bhi[np][0], bhi[np][1], bhi[np][2], bhi[np][3], smem_u32(base + OFF_BHI + rbase));
            LDSM_X4(blo[np][0], blo[np][1], blo[np][2], blo[np][3], smem_u32(base + OFF_BLO + rbase));
        }
        #pragma unroll
        for (int mf = 0; mf < 4; mf++) {
            #pragma unroll
            for (int nf = 0; nf < 4; nf++) {
                int np = nf >> 1, h8 = nf & 1;
                MMA_BF16(acc[mf][nf], ahi[mf], bhi[np][h8], bhi[np][h8 + 2]);
                MMA_BF16(acc[mf][nf], ahi[mf], blo[np][h8], blo[np][h8 + 2]);
                MMA_BF16(acc[mf][nf], alo[mf], bhi[np][h8], bhi[np][h8 + 2]);
            }
        }
    }
}

// ---- big GEMM: XO[v][b][g], cp.async 2-stage pipeline (unchanged from R8) ----
__global__ __launch_bounds__(256) void k_gemm_mma(const float* __restrict__ kb,
                                                  const float* __restrict__ time_,
                                                  const int* __restrict__ node_ids) {
    extern __shared__ char dsm[];
    const int tid = threadIdx.x;
    const int lane = tid & 31, wid = tid >> 5;
    const int wm = wid >> 2, wn = wid & 3;
    const int m0 = blockIdx.x * 128, n0 = blockIdx.y * 128;
    const int NC = CND / 32;

    float acc[4][4][4];
    #pragma unroll
    for (int i = 0; i < 4; i++)
        #pragma unroll
        for (int j = 0; j < 4; j++)
            #pragma unroll
            for (int z = 0; z < 4; z++) acc[i][j][z] = 0.f;

    auto load_stage = [&](int kc, int stage) {
        #pragma unroll
        for (int it = 0; it < 2; it++) {
            int s = tid + it * 256;
            int row = s >> 2, q = s & 3;
            int nb = kc >> 2;
            int off = (kc & 3) * 32 + q * 8;
            int id = node_ids[(m0 + row) * CN + nb];
            uint32_t d = smem_u32(dsm + stage * STG + row * 80 + q * 16);
            CP16(d + OFF_AHI, (const char*)(g_ehi + (size_t)id * CD + off));
            CP16(d + OFF_ALO, (const char*)(g_elo + (size_t)id * CD + off));
            int g = n0 + row;
            int gc = g < CG ? g : (CG - 1);
            uint32_t sz = g < CG ? 16u : 0u;
            CP16Z(d + OFF_BHI, (const char*)(g_kwhi + (size_t)gc * CND + kc * 32 + q * 8), sz);
            CP16Z(d + OFF_BLO, (const char*)(g_kwlo + (size_t)gc * CND + kc * 32 + q * 8), sz);
        }
    };

    load_stage(0, 0); CP_COMMIT();
    load_stage(1, 1); CP_COMMIT();
    for (int kc = 0; kc < NC; kc++) {
        if (kc == NC - 1) { CP_WAIT0(); } else { CP_WAIT1(); }
        __syncthreads();
        mma_chunk(dsm + (kc & 1) * STG, lane, wm, wn, acc);
        __syncthreads();
        if (kc + 2 < NC) { load_stage(kc + 2, (kc + 2) & 1); CP_COMMIT(); }
    }

    #pragma unroll
    for (int mf = 0; mf < 4; mf++) {
        #pragma unroll
        for (int hf = 0; hf < 2; hf++) {
            int r = m0 + wm * 64 + mf * 16 + (lane >> 2) + hf * 8;
            int b = r / CV, v = r - b * CV;
            float t = time_[r];
            float* dst = g_XO + ((size_t)v * CB + b) * CG;
            #pragma unroll
            for (int nf = 0; nf < 4; nf++) {
                int g = n0 + wn * 32 + nf * 8 + (lane & 3) * 2;
                float c0 = acc[mf][nf][hf * 2 + 0];
                float c1 = acc[mf][nf][hf * 2 + 1];
                if (g < CG)     dst[g]     = c0 + t * g_kwlast[g] + kb[g];
                if (g + 1 < CG) dst[g + 1] = c1 + t * g_kwlast[g + 1] + kb[g + 1];
            }
        }
    }
}

// ---- per-step rec GEMM: BM=64 BN=64 BK=16, 256 threads, 100 blocks,
//      register double-buffered global loads ----
__global__ __launch_bounds__(256) void k_rec(const float* __restrict__ rw,
                                             const float* __restrict__ rb,
                                             const float* __restrict__ time_, int v) {
    __shared__ float As[16][68];
    __shared__ float Bs[16][68];
    const int tid = threadIdx.x;
    const int m0 = blockIdx.x * 64, n0 = blockIdx.y * 64;
    const int tx = tid & 15, ty = tid >> 4;
    const int row = tid >> 2, c4 = (tid & 3) * 4;
    const int gB = n0 + row;
    const bool bok = gB < CG;
    const float* ap = g_h + (m0 + row) * CHH + c4;
    const float* bp = g_rwf + (size_t)gB * CHH + c4;

    float acc[4][4];
    #pragma unroll
    for (int i = 0; i < 4; i++)
        #pragma unroll
        for (int j = 0; j < 4; j++) acc[i][j] = 0.f;

    float4 na = *(const float4*)ap;
    float4 nb = bok ? *(const float4*)bp : make_float4(0.f, 0.f, 0.f, 0.f);

    #pragma unroll 1
    for (int it = 0; it < CHH / 16; it++) {
        As[c4 + 0][row] = na.x; As[c4 + 1][row] = na.y;
        As[c4 + 2][row] = na.z; As[c4 + 3][row] = na.w;
        Bs[c4 + 0][row] = nb.x; Bs[c4 + 1][row] = nb.y;
        Bs[c4 + 2][row] = nb.z; Bs[c4 + 3][row] = nb.w;
        __syncthreads();
        if (it + 1 < CHH / 16) {
            na = *(const float4*)(ap + (it + 1) * 16);
            nb = bok ? *(const float4*)(bp + (it + 1) * 16) : make_float4(0.f, 0.f, 0.f, 0.f);
        }
        #pragma unroll
        for (int k = 0; k < 16; k++) {
            float4 a = *(const float4*)&As[k][ty * 4];
            float4 b = *(const float4*)&Bs[k][tx * 4];
            float av[4] = {a.x, a.y, a.z, a.w};
            float bv[4] = {b.x, b.y, b.z, b.w};
            #pragma unroll
            for (int i = 0; i < 4; i++)
                #pragma unroll
                for (int j = 0; j < 4; j++) acc[i][j] += av[i] * bv[j];
        }
        __syncthreads();
    }
    #pragma unroll
    for (int i = 0; i < 4; i++) {
        int bb = m0 + ty * 4 + i;
        float t = time_[bb * CV + v];
        const float* xop = g_XO + ((size_t)v * CB + bb) * CG;
        #pragma unroll
        for (int j = 0; j < 4; j++) {
            int g = n0 + tx * 4 + j;
            if (g < CG)
                g_xo[bb * CG + g] = acc[i][j] + t * rw[(size_t)g * (CHH + 1) + CHH]
                                  + rb[g] + xop[g];
        }
    }
}

// ---- gate (R8 version: emits lh as bf16 hi/lo) ----
__global__ __launch_bounds__(CHH) void k_gate(const float* __restrict__ sw,
                                              const float* __restrict__ sb,
                                              const float* __restrict__ rsw,
                                              const float* __restrict__ rsb,
                                              int v, float* __restrict__ out) {
    const int b = blockIdx.x;
    const int t = threadIdx.x;
    const int slot = v % CCS;
    __shared__ float s24[24];
    __shared__ float sfm[CL], sim[CL];
    __shared__ float sld[CCS];
    __shared__ float smh[CHH];
    __shared__ float ss1[CHS];
    __shared__ float red[6][CHS];

    const float* xo = g_xo + b * CG;
    if (t < 24) s24[t] = xo[t];
    __syncthreads();

    if (t == 0) {
        float m1 = s24[0];
        #pragma unroll
        for (int l = 1; l < CL; l++) m1 = fmaxf(m1, s24[l]);
        float e1[CL], sum1 = 0.f;
        #pragma unroll
        for (int l = 0; l < CL; l++) { e1[l] = expf(s24[l] - m1); sum1 += e1[l]; }
        float inv1 = 1.f / sum1, cum = 0.f, fmsum = 0.f;
        #pragma unroll
        for (int l = 0; l < CL; l++) { cum += e1[l] * inv1; sfm[l] = cum; fmsum += cum; }
        float m2 = s24[12];
        #pragma unroll
        for (int l = 1; l < CL; l++) m2 = fmaxf(m2, s24[12 + l]);
        float e2[CL], sum2 = 0.f;
        #pragma unroll
        for (int l = 0; l < CL; l++) { e2[l] = expf(s24[12 + l] - m2); sum2 += e2[l]; }
        float inv2 = 1.f / sum2, cum2 = 0.f;
        for (int l = CL - 1; l >= 0; l--) { cum2 += e2[l] * inv2; sim[l] = cum2; }
        float dist = 1.f - fmsum / (float)CL;
        g_tmpdis[slot * CB + b] = dist;
        out[CB * COUT + v * CB + b] = dist;
    }
    __syncthreads();

    {
        int l = t >> 5;
        float f  = sigmoidf(xo[24 + t]);
        float i_ = sigmoidf(xo[24 + CHH + t]);
        float o  = sigmoidf(xo[24 + 2 * CHH + t]);
        float ci = tanhf(xo[24 + 3 * CHH + t]);
        float cl = g_c[b * CHH + t];
        float fmv = sfm[l], imv = sim[l], ov = fmv * imv;
        float cnew = ov * (f * cl + i_ * ci) + (fmv - ov) * cl + (imv - ov) * ci;
        float hnew = o * tanhf(cnew);
        g_c[b * CHH + t] = cnew;
        g_h[b * CHH + t] = hnew;
        g_h_all[((size_t)v * CB + b) * CHH + t] = hnew;
    }
    __syncthreads();

    if (t == 0) {
        float cumv[CCS];
        float cum = 0.f;
        #pragma unroll
        for (int k = 0; k < CCS; k++) {
            int s = v - (CCS - 1) + k;
            float d = (s >= 0) ? g_tmpdis[(s % CCS) * CB + b] : 0.f;
            cum += d;
            cumv[k] = cum;
        }
        float mx = cumv[0];
        #pragma unroll
        for (int k = 1; k < CCS; k++) mx = fmaxf(mx, cumv[k]);
        float e[CCS], sum = 0.f;
        #pragma unroll
        for (int k = 0; k < CCS; k++) { e[k] = expf(cumv[k] - mx); sum += e[k]; }
        float inv = 1.f / sum;
        #pragma unroll
        for (int k = 0; k < CCS; k++) sld[k] = e[k] * inv;
    }
    __syncthreads();

    {
        float mh = 0.f;
        __nv_bfloat16 lhi[CCS], llo[CCS];
        #pragma unroll
        for (int k = 0; k < CCS; k++) {
            int s = v - (CCS - 1) + k;
            float hv = (s >= 0) ? g_h_all[((size_t)s * CB + b) * CHH + t] : 0.f;
            float lv = hv * sld[k];
            __nv_bfloat16 hi = __float2bfloat16(lv);
            lhi[k] = hi;
            llo[k] = __float2bfloat16(lv - __bfloat162float(hi));
            mh += lv;
        }
        size_t base = ((size_t)v * CB + b) * CKLH + t * CCS;
        #pragma unroll
        for (int k = 0; k < CCS; k++) { g_lhhi[base + k] = lhi[k]; g_lhlo[base + k] = llo[k]; }
        smh[t] = mh * (1.f / (float)CCS);
    }
    __syncthreads();

    {
        int j = t & 63, seg = t >> 6;
        float p = 0.f;
        #pragma unroll
        for (int h = 0; h < 64; h++) p += smh[seg * 64 + h] * sw[j * CHH + seg * 64 + h];
        red[seg][j] = p;
    }
    __syncthreads();
    if (t < CHS) {
        float a = sb[t];
        #pragma unroll
        for (int z = 0; z < 6; z++) a += red[z][t];
        ss1[t] = fmaxf(a, 0.f);
    }
    __syncthreads();

    {
        float a = rsb[t];
        #pragma unroll
        for (int j = 0; j < CHS; j++) a += ss1[j] * rsw[t * CHS + j];
        g_theme_all[((size_t)v * CB + b) * CHH + t] = sigmoidf(a);
    }
}

// ---- conv GEMM (unchanged from R8) ----
__global__ __launch_bounds__(256) void k_conv_mma(const float* __restrict__ cb) {
    extern __shared__ char dsm[];
    const int tid = threadIdx.x;
    const int lane = tid & 31, wid = tid >> 5;
    const int wm = wid >> 2, wn = wid & 3;
    const int m0 = blockIdx.x * 128, n0 = blockIdx.y * 128;
    const int NC = CKLH / 32;

    float acc[4][4][4];
    #pragma unroll
    for (int i = 0; i < 4; i++)
        #pragma unroll
        for (int j = 0; j < 4; j++)
            #pragma unroll
            for (int z = 0; z < 4; z++) acc[i][j][z] = 0.f;

    auto load_stage = [&](int kc, int stage) {
        #pragma unroll
        for (int it = 0; it < 2; it++) {
            int s = tid + it * 256;
            int row = s >> 2, q = s & 3;
            uint32_t d = smem_u32(dsm + stage * STG + row * 80 + q * 16);
            size_t aoff = (size_t)(m0 + row) * CKLH + kc * 32 + q * 8;
            CP16(d + OFF_AHI, (const char*)(g_lhhi + aoff));
            CP16(d + OFF_ALO, (const char*)(g_lhlo + aoff));
            size_t boff = (size_t)(n0 + row) * CKLH + kc * 32 + q * 8;
            CP16(d + OFF_BHI, (const char*)(g_cwhi + boff));
            CP16(d + OFF_BLO, (const char*)(g_cwlo + boff));
        }
    };

    load_stage(0, 0); CP_COMMIT();
    load_stage(1, 1); CP_COMMIT();
    for (int kc = 0; kc < NC; kc++) {
        if (kc == NC - 1) { CP_WAIT0(); } else { CP_WAIT1(); }
        __syncthreads();
        mma_chunk(dsm + (kc & 1) * STG, lane, wm, wn, acc);
        __syncthreads();
        if (kc + 2 < NC) { load_stage(kc + 2, (kc + 2) & 1); CP_COMMIT(); }
    }

    #pragma unroll
    for (int mf = 0; mf < 4; mf++) {
        #pragma unroll
        for (int hf = 0; hf < 2; hf++) {
            int r = m0 + wm * 64 + mf * 16 + (lane >> 2) + hf * 8;
            int v = r >> 8, b = r & (CB - 1);
            const float* th = g_theme_all + (size_t)r * CHH;
            const float* hn = g_h_all + (size_t)r * CHH;
            float* dst = g_rnn + ((size_t)b * CV + v) * CHH;
            #pragma unroll
            for (int nf = 0; nf < 4; nf++) {
                int o = n0 + wn * 32 + nf * 8 + (lane & 3) * 2;
                float c0 = acc[mf][nf][hf * 2 + 0] + cb[o];
                float c1 = acc[mf][nf][hf * 2 + 1] + cb[o + 1];
                dst[o]     = th[o] * c0 + hn[o];
                dst[o + 1] = th[o + 1] * c1 + hn[o + 1];
            }
        }
    }
}

// ---- output GEMM (unchanged from R8) ----
__global__ __launch_bounds__(256) void k_out(const float* __restrict__ ow,
                                             float* __restrict__ out) {
    __shared__ float As[8][64];
    __shared__ float Bs[8][128];
    const int tid = threadIdx.x;
    const int m0 = blockIdx.x * 64;
    const int KK = CV * CHH;
    const int kbase = blockIdx.z * (KK / SPLITO);
    const int tx = tid & 15, ty = tid >> 4;
    const int arow = tid >> 2, ac2 = (tid & 3) * 2;
    const int brow = tid >> 1, bc4 = (tid & 1) * 4;
    float acc[4][8];
    #pragma unroll
    for (int i = 0; i < 4; i++)
        #pragma unroll
        for (int j = 0; j < 8; j++) acc[i][j] = 0.f;

    for (int kt = 0; kt < (KK / SPLITO) / 8; kt++) {
        int k0 = kbase + kt * 8;
        float2 va = *(const float2*)(g_rnn + (size_t)(m0 + arow) * KK + k0 + ac2);
        float4 vb = *(const float4*)(ow + (size_t)brow * KK + k0 + bc4);
        As[ac2 + 0][arow] = va.x;
        As[ac2 + 1][arow] = va.y;
        Bs[bc4 + 0][brow] = vb.x; Bs[bc4 + 1][brow] = vb.y;
        Bs[bc4 + 2][brow] = vb.z; Bs[bc4 + 3][brow] = vb.w;
        __syncthreads();
        #pragma unroll
        for (int k = 0; k < 8; k++) {
            float4 a = *(const float4*)&As[k][ty * 4];
            float4 c0 = *(const float4*)&Bs[k][tx * 8];
            float4 c1 = *(const float4*)&Bs[k][tx * 8 + 4];
            float av[4] = {a.x, a.y, a.z, a.w};
            float bv[8] = {c0.x, c0.y, c0.z, c0.w, c1.x, c1.y, c1.z, c1.w};
            #pragma unroll
            for (int i = 0; i < 4; i++)
                #pragma unroll
                for (int j = 0; j < 8; j++) acc[i][j] += av[i] * bv[j];
        }
        __syncthreads();
    }
    #pragma unroll
    for (int i = 0; i < 4; i++) {
        int bb = m0 + ty * 4 + i;
        #pragma unroll
        for (int j = 0; j < 8; j++) {
            atomicAdd(&out[bb * COUT + tx * 8 + j], acc[i][j]);
        }
    }
}

extern "C" void kernel_launch(void* const* d_in, const int* in_sizes, int n_in,
                              void* d_out, int out_size) {
    const int*   node_ids = (const int*)d_in[0];
    const float* time_    = (const float*)d_in[3];
    const float* embed    = (const float*)d_in[6];
    const float* kw  = (const float*)d_in[7];
    const float* kb  = (const float*)d_in[8];
    const float* rw  = (const float*)d_in[9];
    const float* rb  = (const float*)d_in[10];
    const float* sw  = (const float*)d_in[11];
    const float* sb  = (const float*)d_in[12];
    const float* rsw = (const float*)d_in[13];
    const float* rsb = (const float*)d_in[14];
    const float* cw  = (const float*)d_in[15];
    const float* cb  = (const float*)d_in[16];
    const float* ow  = (const float*)d_in[17];
    const float* ob  = (const float*)d_in[18];
    float* out = (float*)d_out;

    cudaFuncSetAttribute(k_gemm_mma, cudaFuncAttributeMaxDynamicSharedMemorySize, DSM_TOTAL);
    cudaFuncSetAttribute(k_conv_mma, cudaFuncAttributeMaxDynamicSharedMemorySize, DSM_TOTAL);

    k_init<<<(CB * CHH + 255) / 256, 256>>>();
    k_outinit<<<(CB * COUT + 255) / 256, 256>>>(ob, out);
    k_cvt_embed<<<(NNE * CD + 255) / 256, 256>>>(embed);
    k_cvt_kw<<<(int)(((size_t)CG * CND + 255) / 256), 256>>>(kw);
    k_cvt_last<<<(CG + 255) / 256, 256>>>(kw);
    k_cvt_cw<<<(CHH * CKLH + 255) / 256, 256>>>(cw);
    k_pack_rw<<<(CG * CHH + 255) / 256, 256>>>(rw);
    k_gemm_mma<<<dim3(CB * CV / 128, 13), 256, DSM_TOTAL>>>(kb, time_, node_ids);
    for (int v = 0; v < CV; v++) {
        k_rec<<<dim3(CB / 64, (CG + 63) / 64), 256>>>(rw, rb, time_, v);
        k_gate<<<CB, CHH>>>(sw, sb, rsw, rsb, v, out);
    }
    k_conv_mma<<<dim3(CB * CV / 128, CHH / 128), 256, DSM_TOTAL>>>(cb);
    k_out<<<dim3(CB / 64, 1, SPLITO), 256>>>(ow, out);
}